// round 1
// baseline (speedup 1.0000x reference)
#include <cuda_runtime.h>
#include <math.h>

#define BATCH 256
#define SEQ 256
#define IN_DIM 128
#define HID 1024
#define OUT_DIM 10
#define KTOT (HID + IN_DIM)   // 1152: [h | x_t] fused A operand

#define BM 32
#define BN 64
#define BK 32

// ping-pong hidden state (2 MB) — __device__ globals are the sanctioned scratch
__device__ float g_h[2][BATCH * HID];

// One recurrence step: h_out = tanh([h_in | x_t] @ [Whh ; Whx] + bh)
// grid = (HID/BN=16, BATCH/BM=8) = 128 CTAs, 128 threads, 4x4 microtile.
__global__ __launch_bounds__(128) void rnn_step(
    const float* __restrict__ x,     // [B, S, I]
    const float* __restrict__ Whh,   // [H, H] row-major (k-major)
    const float* __restrict__ Whx,   // [I, H]
    const float* __restrict__ bh,    // [H]
    int t)
{
    __shared__ float As[BM][BK + 1];   // +1 pad: conflict-free scalar access
    __shared__ float Bs[BK][BN];

    const float* hin  = g_h[t & 1];
    float*       hout = g_h[(t & 1) ^ 1];

    const int bm  = blockIdx.y * BM;
    const int bn  = blockIdx.x * BN;
    const int tid = threadIdx.x;
    const int ty  = tid >> 4;     // 0..7  -> 4 rows each
    const int tx  = tid & 15;     // 0..15 -> 4 cols each

    float acc[4][4] = {};

    // t==0: h0 == 0, so skip all Whh k-tiles (also avoids reading uninit g_h)
    const int kstart = (t == 0) ? HID : 0;

    for (int k0 = kstart; k0 < KTOT; k0 += BK) {
        // ---- A tile: rows bm..bm+31, k-slice k0..k0+31 ----
        const float* Asrc;
        long astride;
        if (k0 < HID) { Asrc = hin + k0;                                astride = HID; }
        else          { Asrc = x + (long)t * IN_DIM + (k0 - HID);       astride = (long)SEQ * IN_DIM; }
        #pragma unroll
        for (int r = 0; r < 2; r++) {
            int idx = tid + r * 128;        // 0..255 float4 slots
            int m   = idx >> 3;             // 0..31
            int kq  = (idx & 7) << 2;       // 0,4,...,28
            float4 v = *(const float4*)(Asrc + (long)(bm + m) * astride + kq);
            As[m][kq + 0] = v.x; As[m][kq + 1] = v.y;
            As[m][kq + 2] = v.z; As[m][kq + 3] = v.w;
        }
        // ---- B tile: k-rows k0..k0+31, cols bn..bn+63 ----
        const float* Bsrc = (k0 < HID) ? (Whh + (long)k0 * HID)
                                       : (Whx + (long)(k0 - HID) * HID);
        #pragma unroll
        for (int r = 0; r < 4; r++) {
            int idx = tid + r * 128;        // 0..511 float4 slots
            int kk  = idx >> 4;             // 0..31
            int nq  = (idx & 15) << 2;      // 0,4,...,60
            *(float4*)&Bs[kk][nq] = *(const float4*)(Bsrc + (long)kk * HID + bn + nq);
        }
        __syncthreads();

        #pragma unroll
        for (int k = 0; k < BK; k++) {
            float4 bv = *(const float4*)&Bs[k][tx << 2];
            float a0 = As[(ty << 2) + 0][k];
            float a1 = As[(ty << 2) + 1][k];
            float a2 = As[(ty << 2) + 2][k];
            float a3 = As[(ty << 2) + 3][k];
            acc[0][0] = fmaf(a0, bv.x, acc[0][0]); acc[0][1] = fmaf(a0, bv.y, acc[0][1]);
            acc[0][2] = fmaf(a0, bv.z, acc[0][2]); acc[0][3] = fmaf(a0, bv.w, acc[0][3]);
            acc[1][0] = fmaf(a1, bv.x, acc[1][0]); acc[1][1] = fmaf(a1, bv.y, acc[1][1]);
            acc[1][2] = fmaf(a1, bv.z, acc[1][2]); acc[1][3] = fmaf(a1, bv.w, acc[1][3]);
            acc[2][0] = fmaf(a2, bv.x, acc[2][0]); acc[2][1] = fmaf(a2, bv.y, acc[2][1]);
            acc[2][2] = fmaf(a2, bv.z, acc[2][2]); acc[2][3] = fmaf(a2, bv.w, acc[2][3]);
            acc[3][0] = fmaf(a3, bv.x, acc[3][0]); acc[3][1] = fmaf(a3, bv.y, acc[3][1]);
            acc[3][2] = fmaf(a3, bv.z, acc[3][2]); acc[3][3] = fmaf(a3, bv.w, acc[3][3]);
        }
        __syncthreads();
    }

    #pragma unroll
    for (int i = 0; i < 4; i++) {
        int m = bm + (ty << 2) + i;
        float* orow = hout + (long)m * HID;
        #pragma unroll
        for (int j = 0; j < 4; j++) {
            int n = bn + (tx << 2) + j;
            orow[n] = tanhf(acc[i][j] + bh[n]);
        }
    }
}

// Final projection + softmax: out[b,:] = softmax(h_final @ Why + bo)
__global__ __launch_bounds__(128) void rnn_out(
    const float* __restrict__ Why,   // [H, O]
    const float* __restrict__ bo,    // [O]
    float* __restrict__ out)         // [B, O]
{
    const int b   = blockIdx.x;
    const int tid = threadIdx.x;
    const float* h = g_h[0];  // t=255 (odd) writes buf[(1)^1] = buf[0]

    float acc[OUT_DIM];
    #pragma unroll
    for (int o = 0; o < OUT_DIM; o++) acc[o] = 0.0f;

    for (int k = tid; k < HID; k += 128) {
        float hv = h[(long)b * HID + k];
        #pragma unroll
        for (int o = 0; o < OUT_DIM; o++)
            acc[o] = fmaf(hv, Why[k * OUT_DIM + o], acc[o]);
    }

    __shared__ float red[128][OUT_DIM];
    #pragma unroll
    for (int o = 0; o < OUT_DIM; o++) red[tid][o] = acc[o];
    __syncthreads();

    for (int s = 64; s > 0; s >>= 1) {
        if (tid < s) {
            #pragma unroll
            for (int o = 0; o < OUT_DIM; o++) red[tid][o] += red[tid + s][o];
        }
        __syncthreads();
    }

    if (tid == 0) {
        float lg[OUT_DIM];
        float mx = -1e30f;
        #pragma unroll
        for (int o = 0; o < OUT_DIM; o++) {
            lg[o] = red[0][o] + bo[o];
            mx = fmaxf(mx, lg[o]);
        }
        float ssum = 0.0f;
        #pragma unroll
        for (int o = 0; o < OUT_DIM; o++) {
            lg[o] = expf(lg[o] - mx);
            ssum += lg[o];
        }
        float inv = 1.0f / ssum;
        #pragma unroll
        for (int o = 0; o < OUT_DIM; o++)
            out[(long)b * OUT_DIM + o] = lg[o] * inv;
    }
}

extern "C" void kernel_launch(void* const* d_in, const int* in_sizes, int n_in,
                              void* d_out, int out_size) {
    const float* x   = (const float*)d_in[0];
    const float* Whx = (const float*)d_in[1];
    const float* Whh = (const float*)d_in[2];
    const float* bh  = (const float*)d_in[3];
    const float* Why = (const float*)d_in[4];
    const float* bo  = (const float*)d_in[5];
    float* out = (float*)d_out;

    dim3 grid(HID / BN, BATCH / BM);   // (16, 8) = 128 CTAs
    for (int t = 0; t < SEQ; t++)
        rnn_step<<<grid, 128>>>(x, Whh, Whx, bh, t);
    rnn_out<<<BATCH, 128>>>(Why, bo, out);
}

// round 3
// speedup vs baseline: 1.5995x; 1.5995x over previous
#include <cuda_runtime.h>
#include <cstdint>
#include <math.h>

#define BATCH 256
#define SEQ 256
#define IN_DIM 128
#define HID 1024
#define OUT_DIM 10
#define KTOT (HID + IN_DIM)   // 1152: [h | x_t] fused A operand

#define BM 32
#define BN 64
#define BK 32
#define APAD 4                // row stride 36 floats = 144B, keeps 16B alignment

// ping-pong hidden state (2 MB) — __device__ globals are the sanctioned scratch
__device__ float g_h[2][BATCH * HID];

__device__ __forceinline__ void cp_async16(void* smem_dst, const void* gmem_src) {
    unsigned int d = (unsigned int)__cvta_generic_to_shared(smem_dst);
    asm volatile("cp.async.ca.shared.global [%0], [%1], 16;\n" :: "r"(d), "l"(gmem_src));
}
__device__ __forceinline__ void cp_async_commit() {
    asm volatile("cp.async.commit_group;\n");
}
template <int N>
__device__ __forceinline__ void cp_async_wait() {
    asm volatile("cp.async.wait_group %0;\n" :: "n"(N));
}

// One recurrence step: h_out = tanh([h_in | x_t] @ [Whh ; Whx] + bh)
// grid = (HID/BN=16, BATCH/BM=8) = 128 CTAs, 128 threads, 4x4 microtile.
// Two-stage cp.async pipeline hides global (L2) latency behind the FFMA body.
__global__ __launch_bounds__(128) void rnn_step(
    const float* __restrict__ x,     // [B, S, I]
    const float* __restrict__ Whh,   // [H, H]
    const float* __restrict__ Whx,   // [I, H]
    const float* __restrict__ bh,    // [H]
    int t)
{
    __shared__ float As[2][BM][BK + APAD];
    __shared__ float Bs[2][BK][BN];

    const float* hin  = g_h[t & 1];
    float*       hout = g_h[(t & 1) ^ 1];

    const int bm  = blockIdx.y * BM;
    const int bn  = blockIdx.x * BN;
    const int tid = threadIdx.x;
    const int ty  = tid >> 4;     // 0..7  -> 4 rows each
    const int tx  = tid & 15;     // 0..15 -> 4 cols each

    // t==0: h0 == 0, skip all Whh k-tiles (also avoids reading uninit g_h)
    const int kstart = (t == 0) ? HID : 0;
    const int ntiles = (KTOT - kstart) / BK;

    auto load_tile = [&](int tile, int buf) {
        const int k0 = kstart + tile * BK;
        const float* Asrc;
        long astride;
        if (k0 < HID) { Asrc = hin + k0;                          astride = HID; }
        else          { Asrc = x + (long)t * IN_DIM + (k0 - HID); astride = (long)SEQ * IN_DIM; }
        #pragma unroll
        for (int r = 0; r < 2; r++) {
            int idx = tid + r * 128;        // 0..255 float4 slots
            int m   = idx >> 3;             // 0..31
            int kq  = (idx & 7) << 2;       // 0,4,...,28
            cp_async16(&As[buf][m][kq], Asrc + (long)(bm + m) * astride + kq);
        }
        const float* Bsrc = (k0 < HID) ? (Whh + (long)k0 * HID)
                                       : (Whx + (long)(k0 - HID) * HID);
        #pragma unroll
        for (int r = 0; r < 4; r++) {
            int idx = tid + r * 128;        // 0..511 float4 slots
            int kk  = idx >> 4;             // 0..31
            int nq  = (idx & 15) << 2;      // 0,4,...,60
            cp_async16(&Bs[buf][kk][nq], Bsrc + (long)kk * HID + bn + nq);
        }
        cp_async_commit();
    };

    float acc[4][4] = {};

    load_tile(0, 0);

    for (int tile = 0; tile < ntiles; tile++) {
        const int buf = tile & 1;
        if (tile + 1 < ntiles) {
            load_tile(tile + 1, buf ^ 1);
            cp_async_wait<1>();   // group for `tile` complete; tile+1 in flight
        } else {
            cp_async_wait<0>();
        }
        __syncthreads();

        #pragma unroll
        for (int k = 0; k < BK; k++) {
            float4 bv = *(const float4*)&Bs[buf][k][tx << 2];
            float a0 = As[buf][(ty << 2) + 0][k];
            float a1 = As[buf][(ty << 2) + 1][k];
            float a2 = As[buf][(ty << 2) + 2][k];
            float a3 = As[buf][(ty << 2) + 3][k];
            acc[0][0] = fmaf(a0, bv.x, acc[0][0]); acc[0][1] = fmaf(a0, bv.y, acc[0][1]);
            acc[0][2] = fmaf(a0, bv.z, acc[0][2]); acc[0][3] = fmaf(a0, bv.w, acc[0][3]);
            acc[1][0] = fmaf(a1, bv.x, acc[1][0]); acc[1][1] = fmaf(a1, bv.y, acc[1][1]);
            acc[1][2] = fmaf(a1, bv.z, acc[1][2]); acc[1][3] = fmaf(a1, bv.w, acc[1][3]);
            acc[2][0] = fmaf(a2, bv.x, acc[2][0]); acc[2][1] = fmaf(a2, bv.y, acc[2][1]);
            acc[2][2] = fmaf(a2, bv.z, acc[2][2]); acc[2][3] = fmaf(a2, bv.w, acc[2][3]);
            acc[3][0] = fmaf(a3, bv.x, acc[3][0]); acc[3][1] = fmaf(a3, bv.y, acc[3][1]);
            acc[3][2] = fmaf(a3, bv.z, acc[3][2]); acc[3][3] = fmaf(a3, bv.w, acc[3][3]);
        }
        __syncthreads();
    }

    #pragma unroll
    for (int i = 0; i < 4; i++) {
        int m = bm + (ty << 2) + i;
        float* orow = hout + (long)m * HID;
        #pragma unroll
        for (int j = 0; j < 4; j++) {
            int n = bn + (tx << 2) + j;
            orow[n] = tanhf(acc[i][j] + bh[n]);
        }
    }
}

// Final projection + softmax: out[b,:] = softmax(h_final @ Why + bo)
__global__ __launch_bounds__(128) void rnn_out(
    const float* __restrict__ Why,   // [H, O]
    const float* __restrict__ bo,    // [O]
    float* __restrict__ out)         // [B, O]
{
    const int b   = blockIdx.x;
    const int tid = threadIdx.x;
    const float* h = g_h[0];  // t=255 (odd) writes buf[(1)^1] = buf[0]

    float acc[OUT_DIM];
    #pragma unroll
    for (int o = 0; o < OUT_DIM; o++) acc[o] = 0.0f;

    for (int k = tid; k < HID; k += 128) {
        float hv = h[(long)b * HID + k];
        #pragma unroll
        for (int o = 0; o < OUT_DIM; o++)
            acc[o] = fmaf(hv, Why[k * OUT_DIM + o], acc[o]);
    }

    __shared__ float red[128][OUT_DIM];
    #pragma unroll
    for (int o = 0; o < OUT_DIM; o++) red[tid][o] = acc[o];
    __syncthreads();

    for (int s = 64; s > 0; s >>= 1) {
        if (tid < s) {
            #pragma unroll
            for (int o = 0; o < OUT_DIM; o++) red[tid][o] += red[tid + s][o];
        }
        __syncthreads();
    }

    if (tid == 0) {
        float lg[OUT_DIM];
        float mx = -1e30f;
        #pragma unroll
        for (int o = 0; o < OUT_DIM; o++) {
            lg[o] = red[0][o] + bo[o];
            mx = fmaxf(mx, lg[o]);
        }
        float ssum = 0.0f;
        #pragma unroll
        for (int o = 0; o < OUT_DIM; o++) {
            lg[o] = expf(lg[o] - mx);
            ssum += lg[o];
        }
        float inv = 1.0f / ssum;
        #pragma unroll
        for (int o = 0; o < OUT_DIM; o++)
            out[(long)b * OUT_DIM + o] = lg[o] * inv;
    }
}

extern "C" void kernel_launch(void* const* d_in, const int* in_sizes, int n_in,
                              void* d_out, int out_size) {
    const float* x   = (const float*)d_in[0];
    const float* Whx = (const float*)d_in[1];
    const float* Whh = (const float*)d_in[2];
    const float* bh  = (const float*)d_in[3];
    const float* Why = (const float*)d_in[4];
    const float* bo  = (const float*)d_in[5];
    float* out = (float*)d_out;

    dim3 grid(HID / BN, BATCH / BM);   // (16, 8) = 128 CTAs
    for (int t = 0; t < SEQ; t++)
        rnn_step<<<grid, 128>>>(x, Whh, Whx, bh, t);
    rnn_out<<<BATCH, 128>>>(Why, bo, out);
}